// round 1
// baseline (speedup 1.0000x reference)
#include <cuda_runtime.h>
#include <cuda_bf16.h>

// ---------------------------------------------------------------------------
// LatentLayer loss, factorized:
//   exp(alpha*d_ij) = G[i,k] * H[i,m] * exp(alpha*|e_j|^2),  j = k*1024 + m
//   C[k,m] = sum_i G[i,k]*H[i,m]   (FP32 FFMA "GEMM", K=8192, out 16x1024)
//   lse_j  = alpha*|e_j|^2 + log(C)
//   loss   = -mean(lse) + (2*ls - 1) + log(N)
// ---------------------------------------------------------------------------

#define N_Z      8192
#define M_EPS    1024
#define N_EMB    16
#define NBLK     296
#define CHUNK    28        // 296*28 = 8288 >= 8192
#define M_TOT    (N_EMB * M_EPS)   // 16384

__device__ float g_C[M_TOT];     // C[k][m], row-major 16 x 1024
__device__ float g_part[64];     // per-block partial sums of lse

__device__ __forceinline__ float ex2f(float x) {
    float y; asm("ex2.approx.ftz.f32 %0, %1;" : "=f"(y) : "f"(x)); return y;
}
__device__ __forceinline__ float lg2f(float x) {
    float y; asm("lg2.approx.ftz.f32 %0, %1;" : "=f"(y) : "f"(x)); return y;
}

// ---------------------------------------------------------------------------
// Kernel 0: zero the accumulator C
// ---------------------------------------------------------------------------
__global__ void zero_kernel() {
    int idx = blockIdx.x * blockDim.x + threadIdx.x;
    if (idx < M_TOT) g_C[idx] = 0.0f;
}

// ---------------------------------------------------------------------------
// Kernel 1: main accumulation.  Grid = NBLK blocks x 256 threads.
// Block b handles i in [b*CHUNK, b*CHUNK+CHUNK).  Thread t owns columns
// m = 4*t .. 4*t+3 (all 1024 columns covered) and ALL 16 k rows:
// 64 register accumulators per thread.
// ---------------------------------------------------------------------------
__global__ __launch_bounds__(256, 2)
void main_kernel(const float* __restrict__ z,
                 const float* __restrict__ emb,
                 const float* __restrict__ lsig,
                 const float* __restrict__ eps,
                 const float* __restrict__ temp)
{
    __shared__ float  sG[CHUNK][N_EMB];   // G[i_local][k]
    __shared__ float2 sZ[CHUNK];          // pre-scaled z: LOG2E*u*T*z_i

    const int   tid = threadIdx.x;
    const float T   = temp[0];
    const float ls  = lsig[0];
    const float u   = __expf(-2.0f * ls);     // 1/sigma^2
    const float alpha = -0.5f * u;
    const float L2E = 1.4426950408889634f;

    const int i0 = blockIdx.x * CHUNK;

    // --- setup: G[i][k] and scaled z in smem ---
    for (int t = tid; t < CHUNK * N_EMB; t += 256) {
        int il = t >> 4;
        int k  = t & 15;
        int i  = i0 + il;
        float g = 0.0f;
        if (i < N_Z) {
            float zx = z[2 * i], zy = z[2 * i + 1];
            float mx = (1.0f - T) * emb[2 * k];
            float my = (1.0f - T) * emb[2 * k + 1];
            float a  = alpha * (zx * zx + zy * zy) + u * (zx * mx + zy * my);
            g = ex2f(L2E * a);
        }
        sG[il][k] = g;
    }
    if (tid < CHUNK) {
        int i = i0 + tid;
        float s  = L2E * u * T;
        float zx = (i < N_Z) ? z[2 * i]     : 0.0f;
        float zy = (i < N_Z) ? z[2 * i + 1] : 0.0f;
        sZ[tid] = make_float2(s * zx, s * zy);
    }
    __syncthreads();

    // --- per-thread eps columns ---
    float2 ep[4];
#pragma unroll
    for (int mm = 0; mm < 4; mm++)
        ep[mm] = reinterpret_cast<const float2*>(eps)[4 * tid + mm];

    float acc[N_EMB][4];
#pragma unroll
    for (int k = 0; k < N_EMB; k++)
#pragma unroll
        for (int mm = 0; mm < 4; mm++) acc[k][mm] = 0.0f;

    // --- main loop over the K-chunk ---
#pragma unroll 2
    for (int il = 0; il < CHUNK; il++) {
        float2 zz = sZ[il];
        float h[4];
#pragma unroll
        for (int mm = 0; mm < 4; mm++)
            h[mm] = ex2f(fmaf(zz.x, ep[mm].x, zz.y * ep[mm].y));

        float4 g0 = *reinterpret_cast<const float4*>(&sG[il][0]);
        float4 g1 = *reinterpret_cast<const float4*>(&sG[il][4]);
        float4 g2 = *reinterpret_cast<const float4*>(&sG[il][8]);
        float4 g3 = *reinterpret_cast<const float4*>(&sG[il][12]);
        float gk[N_EMB] = {g0.x, g0.y, g0.z, g0.w, g1.x, g1.y, g1.z, g1.w,
                           g2.x, g2.y, g2.z, g2.w, g3.x, g3.y, g3.z, g3.w};
#pragma unroll
        for (int k = 0; k < N_EMB; k++)
#pragma unroll
            for (int mm = 0; mm < 4; mm++)
                acc[k][mm] = fmaf(gk[k], h[mm], acc[k][mm]);
    }

    // --- epilogue: accumulate into global C ---
#pragma unroll
    for (int k = 0; k < N_EMB; k++)
#pragma unroll
        for (int mm = 0; mm < 4; mm++)
            atomicAdd(&g_C[k * M_EPS + 4 * tid + mm], acc[k][mm]);
}

// ---------------------------------------------------------------------------
// Kernel 2: lse per column + per-block partial sums.  64 blocks x 256.
// ---------------------------------------------------------------------------
__global__ void reduce_kernel(const float* __restrict__ emb,
                              const float* __restrict__ eps,
                              const float* __restrict__ lsig,
                              const float* __restrict__ temp)
{
    __shared__ float sred[256];
    const int tid = threadIdx.x;
    const int j   = blockIdx.x * 256 + tid;
    const int k   = j >> 10;
    const int m   = j & 1023;

    const float T  = temp[0];
    const float ls = lsig[0];
    const float u  = __expf(-2.0f * ls);
    const float alpha = -0.5f * u;
    const float LN2 = 0.6931471805599453f;

    float ex = (1.0f - T) * emb[2 * k]     + T * eps[2 * m];
    float ey = (1.0f - T) * emb[2 * k + 1] + T * eps[2 * m + 1];
    float lse = alpha * (ex * ex + ey * ey) + lg2f(g_C[j]) * LN2;

    sred[tid] = lse;
    __syncthreads();
    for (int s = 128; s > 0; s >>= 1) {
        if (tid < s) sred[tid] += sred[tid + s];
        __syncthreads();
    }
    if (tid == 0) g_part[blockIdx.x] = sred[0];
}

// ---------------------------------------------------------------------------
// Kernel 3: finalize.  1 block x 64 threads.
// ---------------------------------------------------------------------------
__global__ void final_kernel(const float* __restrict__ lsig,
                             float* __restrict__ out)
{
    __shared__ float s[64];
    const int tid = threadIdx.x;
    s[tid] = g_part[tid];
    __syncthreads();
    for (int st = 32; st > 0; st >>= 1) {
        if (tid < st) s[tid] += s[tid + st];
        __syncthreads();
    }
    if (tid == 0) {
        float ls = lsig[0];
        out[0] = -s[0] / (float)M_TOT + (2.0f * ls - 1.0f) + logf((float)N_Z);
    }
}

// ---------------------------------------------------------------------------
extern "C" void kernel_launch(void* const* d_in, const int* in_sizes, int n_in,
                              void* d_out, int out_size)
{
    const float* z    = (const float*)d_in[0];
    const float* emb  = (const float*)d_in[1];
    const float* lsig = (const float*)d_in[2];
    const float* eps  = (const float*)d_in[3];
    const float* temp = (const float*)d_in[4];
    float* out = (float*)d_out;

    zero_kernel<<<(M_TOT + 1023) / 1024, 1024>>>();
    main_kernel<<<NBLK, 256>>>(z, emb, lsig, eps, temp);
    reduce_kernel<<<64, 256>>>(emb, eps, lsig, temp);
    final_kernel<<<1, 64>>>(lsig, out);
}

// round 3
// speedup vs baseline: 2.0164x; 2.0164x over previous
#include <cuda_runtime.h>
#include <cuda_bf16.h>

// ---------------------------------------------------------------------------
// LatentLayer loss, factorized, single fused kernel:
//   exp(alpha*d_ij) = G[i,k] * H[i,m] * exp(alpha*|e_j|^2),  j = k*1024 + m
//   C[k,m] = sum_i G[i,k]*H[i,m]   (FP32 f32x2 FFMA "GEMM", K=8192, out 16x1024)
//   lse_j  = alpha*|e_j|^2 + ln(C[k,m])
//   loss   = -mean(lse) + (2*ls - 1) + ln(N)
// Last-block pattern: after all blocks red.v4 their partials into g_C, the
// final arriving block computes the lse reduction, writes out[0], and
// re-zeroes g_C / g_done for the next graph replay (g_C starts zeroed in .bss).
// ---------------------------------------------------------------------------

#define N_Z      8192
#define M_EPS    1024
#define N_EMB    16
#define NBLK     296
#define CHUNK    28        // 296*28 = 8288 >= 8192
#define M_TOT    (N_EMB * M_EPS)   // 16384

__device__ __align__(16) float g_C[M_TOT];   // zero-initialized .bss
__device__ unsigned int g_done = 0;

__device__ __forceinline__ float ex2f(float x) {
    float y; asm("ex2.approx.ftz.f32 %0, %1;" : "=f"(y) : "f"(x)); return y;
}
__device__ __forceinline__ float lg2f(float x) {
    float y; asm("lg2.approx.ftz.f32 %0, %1;" : "=f"(y) : "f"(x)); return y;
}
__device__ __forceinline__ unsigned long long pack2(float lo, float hi) {
    unsigned long long r;
    asm("mov.b64 %0, {%1, %2};" : "=l"(r) : "f"(lo), "f"(hi));
    return r;
}
__device__ __forceinline__ void unpack2(unsigned long long v, float& lo, float& hi) {
    asm("mov.b64 {%0, %1}, %2;" : "=f"(lo), "=f"(hi) : "l"(v));
}
__device__ __forceinline__ unsigned long long fma2(unsigned long long a,
                                                   unsigned long long b,
                                                   unsigned long long c) {
    unsigned long long d;
    asm("fma.rn.f32x2 %0, %1, %2, %3;" : "=l"(d) : "l"(a), "l"(b), "l"(c));
    return d;
}
__device__ __forceinline__ unsigned long long mul2(unsigned long long a,
                                                   unsigned long long b) {
    unsigned long long d;
    asm("mul.rn.f32x2 %0, %1, %2;" : "=l"(d) : "l"(a), "l"(b));
    return d;
}

__global__ __launch_bounds__(256, 2)
void fused_kernel(const float* __restrict__ z,
                  const float* __restrict__ emb,
                  const float* __restrict__ lsig,
                  const float* __restrict__ eps,
                  const float* __restrict__ temp,
                  float* __restrict__ out)
{
    __shared__ float2 sGd[CHUNK][N_EMB];  // G duplicated: (g, g) pairs
    __shared__ float2 sZ[CHUNK];          // pre-scaled z: LOG2E*u*T*z_i
    __shared__ float  sred[256];
    __shared__ int    sIsLast;

    const int   tid = threadIdx.x;
    const float T   = temp[0];
    const float ls  = lsig[0];
    const float u   = __expf(-2.0f * ls);       // 1/sigma^2
    const float alpha = -0.5f * u;
    const float L2E = 1.4426950408889634f;
    const float LN2 = 0.6931471805599453f;

    const int i0 = blockIdx.x * CHUNK;

    // --- prologue: G[i][k] duplicated, scaled z in smem ---
    for (int t = tid; t < CHUNK * N_EMB; t += 256) {
        int il = t >> 4;
        int k  = t & 15;
        int i  = i0 + il;
        float g = 0.0f;
        if (i < N_Z) {
            float zx = z[2 * i], zy = z[2 * i + 1];
            float mx = (1.0f - T) * emb[2 * k];
            float my = (1.0f - T) * emb[2 * k + 1];
            float a  = alpha * (zx * zx + zy * zy) + u * (zx * mx + zy * my);
            g = ex2f(L2E * a);
        }
        sGd[il][k] = make_float2(g, g);
    }
    if (tid < CHUNK) {
        int i = i0 + tid;
        float s  = L2E * u * T;
        float zx = (i < N_Z) ? z[2 * i]     : 0.0f;
        float zy = (i < N_Z) ? z[2 * i + 1] : 0.0f;
        sZ[tid] = make_float2(s * zx, s * zy);
    }
    __syncthreads();

    // --- per-thread columns, rotated per block to spread LTS atomic traffic ---
    const int mbase = 4 * ((tid + blockIdx.x) & 255);

    // eps columns m..m+3, packed by component: (x0,x1),(x2,x3),(y0,y1),(y2,y3)
    float4 q0 = *reinterpret_cast<const float4*>(&eps[2 * mbase]);      // x0,y0,x1,y1
    float4 q1 = *reinterpret_cast<const float4*>(&eps[2 * mbase + 4]);  // x2,y2,x3,y3
    const unsigned long long epx01 = pack2(q0.x, q0.z);
    const unsigned long long epy01 = pack2(q0.y, q0.w);
    const unsigned long long epx23 = pack2(q1.x, q1.z);
    const unsigned long long epy23 = pack2(q1.y, q1.w);

    unsigned long long acc01[N_EMB], acc23[N_EMB];
#pragma unroll
    for (int k = 0; k < N_EMB; k++) { acc01[k] = 0ull; acc23[k] = 0ull; }

    // --- main loop: 36 f32x2-fma-pipe ops + 4 MUFU + 8 LDS.128 per iter ---
#pragma unroll 4
    for (int il = 0; il < CHUNK; il++) {
        float2 zz = sZ[il];
        unsigned long long zx2 = pack2(zz.x, zz.x);
        unsigned long long zy2 = pack2(zz.y, zz.y);
        unsigned long long ha01 = fma2(zx2, epx01, mul2(zy2, epy01));
        unsigned long long ha23 = fma2(zx2, epx23, mul2(zy2, epy23));
        float a0, a1, a2, a3;
        unpack2(ha01, a0, a1);
        unpack2(ha23, a2, a3);
        unsigned long long h01 = pack2(ex2f(a0), ex2f(a1));
        unsigned long long h23 = pack2(ex2f(a2), ex2f(a3));

#pragma unroll
        for (int k2 = 0; k2 < N_EMB / 2; k2++) {
            ulonglong2 gg = *reinterpret_cast<const ulonglong2*>(&sGd[il][2 * k2]);
            acc01[2 * k2]     = fma2(gg.x, h01, acc01[2 * k2]);
            acc23[2 * k2]     = fma2(gg.x, h23, acc23[2 * k2]);
            acc01[2 * k2 + 1] = fma2(gg.y, h01, acc01[2 * k2 + 1]);
            acc23[2 * k2 + 1] = fma2(gg.y, h23, acc23[2 * k2 + 1]);
        }
    }

    // --- epilogue: vector reductions into global C ---
#pragma unroll
    for (int k = 0; k < N_EMB; k++) {
        float c0, c1, c2, c3;
        unpack2(acc01[k], c0, c1);
        unpack2(acc23[k], c2, c3);
        asm volatile("red.global.add.v4.f32 [%0], {%1, %2, %3, %4};"
                     :: "l"(&g_C[k * M_EPS + mbase]),
                        "f"(c0), "f"(c1), "f"(c2), "f"(c3)
                     : "memory");
    }
    __threadfence();

    if (tid == 0) {
        unsigned int ticket = atomicAdd(&g_done, 1u);
        sIsLast = (ticket == NBLK - 1);
    }
    __syncthreads();
    if (!sIsLast) return;

    // ===== last block: lse over all 16384 columns, reduce, finalize =====
    __threadfence();   // acquire side: see all red.v4 results
    float sum = 0.0f;
    for (int q = 0; q < M_TOT / 256; q++) {
        int j = q * 256 + tid;
        int k = j >> 10;
        int m = j & 1023;
        float ex = (1.0f - T) * emb[2 * k]     + T * eps[2 * m];
        float ey = (1.0f - T) * emb[2 * k + 1] + T * eps[2 * m + 1];
        float c  = g_C[j];
        g_C[j] = 0.0f;    // reset for next replay
        sum += alpha * (ex * ex + ey * ey) + lg2f(c) * LN2;
    }
    sred[tid] = sum;
    __syncthreads();
#pragma unroll
    for (int s = 128; s > 0; s >>= 1) {
        if (tid < s) sred[tid] += sred[tid + s];
        __syncthreads();
    }
    if (tid == 0) {
        g_done = 0;       // reset counter for next replay
        out[0] = -sred[0] / (float)M_TOT + (2.0f * ls - 1.0f) + logf((float)N_Z);
    }
}

// ---------------------------------------------------------------------------
extern "C" void kernel_launch(void* const* d_in, const int* in_sizes, int n_in,
                              void* d_out, int out_size)
{
    const float* z    = (const float*)d_in[0];
    const float* emb  = (const float*)d_in[1];
    const float* lsig = (const float*)d_in[2];
    const float* eps  = (const float*)d_in[3];
    const float* temp = (const float*)d_in[4];
    float* out = (float*)d_out;

    fused_kernel<<<NBLK, 256>>>(z, emb, lsig, eps, temp, out);
}